// round 1
// baseline (speedup 1.0000x reference)
#include <cuda_runtime.h>
#include <cuda_bf16.h>
#include <cstdint>

// Sobel conv (cross-correlation, SAME zero padding) + sign-difference maps.
// x:  [B,1,H,W] fp32
// y:  [B,2,H,W]         y[:,0]=Gx response, y[:,1]=Gy response
// y0: [B,1,H-1,W-1]     sign(y0_ch)[..,w] - sign(y0_ch)[..,w+1], rows 0..H-2
// y1: [B,1,H-1,W-1]     sign(y1_ch)[h,..] - sign(y1_ch)[h+1,..], cols 0..W-2

#define IMG_H 1024
#define IMG_W 1024
#define TH 8
#define TW 32
// smem tile covers rows h0-1 .. h0+TH+1  (TH+3 rows)
//                   cols w0-1 .. w0+TW+1  (TW+3 cols)
#define SMH (TH + 3)
#define SMW (TW + 3)

__device__ __forceinline__ float fsign(float v) {
    return (float)((v > 0.0f) - (v < 0.0f));
}

__global__ __launch_bounds__(TW * TH)
void sobel_sign_kernel(const float* __restrict__ x,
                       float* __restrict__ y,
                       float* __restrict__ y0,
                       float* __restrict__ y1) {
    __shared__ float t[SMH][SMW + 1];  // +1 pad: avoid bank conflicts

    const int b  = blockIdx.z;
    const int h0 = blockIdx.y * TH;
    const int w0 = blockIdx.x * TW;

    const float* __restrict__ xb = x + (size_t)b * IMG_H * IMG_W;

    // Cooperative load of (SMH x SMW) halo tile with zero padding.
    const int tid = threadIdx.y * TW + threadIdx.x;
    #pragma unroll
    for (int i = tid; i < SMH * SMW; i += TW * TH) {
        const int r = i / SMW;
        const int c = i - r * SMW;
        const int hh = h0 - 1 + r;
        const int ww = w0 - 1 + c;
        float v = 0.0f;
        if (hh >= 0 && hh < IMG_H && ww >= 0 && ww < IMG_W)
            v = __ldg(&xb[(size_t)hh * IMG_W + ww]);
        t[r][c] = v;
    }
    __syncthreads();

    const int tx = threadIdx.x;
    const int ty = threadIdx.y;
    const int h = h0 + ty;
    const int w = w0 + tx;

    // smem center of pixel (h,w) is t[ty+1][tx+1]
    const int r = ty + 1;
    const int c = tx + 1;

    // Gx at (h,w):  (left col) - (right col), rows weighted 1,2,1
    const float gx = (t[r-1][c-1] + 2.0f * t[r][c-1] + t[r+1][c-1])
                   - (t[r-1][c+1] + 2.0f * t[r][c+1] + t[r+1][c+1]);
    // Gy at (h,w):  (top row) - (bottom row), cols weighted 1,2,1
    const float gy = (t[r-1][c-1] + 2.0f * t[r-1][c] + t[r-1][c+1])
                   - (t[r+1][c-1] + 2.0f * t[r+1][c] + t[r+1][c+1]);

    float* __restrict__ yb = y + (size_t)b * 2 * IMG_H * IMG_W;
    yb[(size_t)h * IMG_W + w] = gx;
    yb[(size_t)IMG_H * IMG_W + (size_t)h * IMG_W + w] = gy;

    if (h < IMG_H - 1 && w < IMG_W - 1) {
        // Gx at (h, w+1): center (r, c+1) -> cols c..c+2 (max tx+3 = SMW-1, in bounds)
        const float gx_r = (t[r-1][c] + 2.0f * t[r][c] + t[r+1][c])
                         - (t[r-1][c+2] + 2.0f * t[r][c+2] + t[r+1][c+2]);
        // Gy at (h+1, w): center (r+1, c) -> rows r..r+2 (max ty+3 = SMH-1, in bounds)
        const float gy_d = (t[r][c-1] + 2.0f * t[r][c] + t[r][c+1])
                         - (t[r+2][c-1] + 2.0f * t[r+2][c] + t[r+2][c+1]);

        const size_t sd = (size_t)(IMG_H - 1) * (IMG_W - 1);
        const size_t o  = (size_t)b * sd + (size_t)h * (IMG_W - 1) + w;
        y0[o] = fsign(gx) - fsign(gx_r);
        y1[o] = fsign(gy) - fsign(gy_d);
    }
}

extern "C" void kernel_launch(void* const* d_in, const int* in_sizes, int n_in,
                              void* d_out, int out_size) {
    const float* x = (const float*)d_in[0];
    const int B = in_sizes[0] / (IMG_H * IMG_W);

    float* y  = (float*)d_out;
    float* y0 = y  + (size_t)B * 2 * IMG_H * IMG_W;
    float* y1 = y0 + (size_t)B * (IMG_H - 1) * (IMG_W - 1);

    dim3 block(TW, TH, 1);
    dim3 grid(IMG_W / TW, IMG_H / TH, B);
    sobel_sign_kernel<<<grid, block>>>(x, y, y0, y1);
}

// round 2
// speedup vs baseline: 1.2566x; 1.2566x over previous
#include <cuda_runtime.h>
#include <cuda_bf16.h>
#include <cstdint>

// Sobel conv (cross-correlation, SAME zero padding) + sign-difference maps.
// y[:,0]=Gx, y[:,1]=Gy ; y0[h,w]=sign(Gx[h,w])-sign(Gx[h,w+1]) ; y1[h,w]=sign(Gy[h,w])-sign(Gy[h+1,w])

#define IMG_H 1024
#define IMG_W 1024
#define TH 8            // output rows per block
#define TXV 32          // threads in x
#define OPT 4           // outputs per thread along W
#define TW (TXV * OPT)  // 128 output cols per block
#define SMH (TH + 3)    // 11 rows (h0-1 .. h0+9)
#define SMW 136         // cols w0-4 .. w0+131 (16B-aligned halo both sides)
#define SM_OFF 4        // smem col of global w0
#define NCH (SMW / 4)   // 34 float4 chunks per row

__device__ __forceinline__ float fsign(float v) {
    return (float)((v > 0.0f) - (v < 0.0f));
}

__global__ __launch_bounds__(TXV * TH)
void sobel_sign_kernel(const float* __restrict__ x,
                       float* __restrict__ y,
                       float* __restrict__ y0,
                       float* __restrict__ y1) {
    __shared__ __align__(16) float t[SMH][SMW];

    const int b  = blockIdx.z;
    const int h0 = blockIdx.y * TH;
    const int w0 = blockIdx.x * TW;

    const float* __restrict__ xb = x + (size_t)b * IMG_H * IMG_W;
    const int tid = threadIdx.y * TXV + threadIdx.x;

    // ---- vectorized halo-tile fill: 11 rows x 34 float4 chunks ----
    #pragma unroll
    for (int i = tid; i < SMH * NCH; i += TXV * TH) {
        const int rr = i / NCH;
        const int cc = i - rr * NCH;
        const int hh = h0 - 1 + rr;
        const int ww = w0 - 4 + cc * 4;
        float4 v = make_float4(0.f, 0.f, 0.f, 0.f);
        if ((unsigned)hh < (unsigned)IMG_H) {
            if (ww >= 0 && ww + 3 < IMG_W) {
                v = *reinterpret_cast<const float4*>(xb + (size_t)hh * IMG_W + ww);
            } else {
                float* ve = reinterpret_cast<float*>(&v);
                #pragma unroll
                for (int e = 0; e < 4; e++) {
                    const int we = ww + e;
                    if ((unsigned)we < (unsigned)IMG_W)
                        ve[e] = xb[(size_t)hh * IMG_W + we];
                }
            }
        }
        *reinterpret_cast<float4*>(&t[rr][cc * 4]) = v;
    }
    __syncthreads();

    const int tx = threadIdx.x;
    const int ty = threadIdx.y;
    const int c  = SM_OFF + tx * OPT;   // smem col of this thread's first output

    float gx0, gx1, gx2, gx3, gxr3;
    float gy0, gy1, gy2, gy3;
    float gd0, gd1, gd2, gd3;

    // Row helper: given smem row sr, produce horizontal diffs/sums.
    // cols: s0 = c-1, v0 = c..c+3, v1 = c+4..c+7  (all 16B-aligned vec loads)
#define ROW_LOAD(sr, s0, v0, v1)                                        \
    const float  s0 = t[sr][c - 1];                                     \
    const float4 v0 = *reinterpret_cast<const float4*>(&t[sr][c]);      \
    const float4 v1 = *reinterpret_cast<const float4*>(&t[sr][c + 4]);

    {   // row r-1 = ty : gx weight 1, gy top (+)
        ROW_LOAD(ty, s0, v0, v1)
        gx0 = s0   - v0.y;  gx1 = v0.x - v0.z;
        gx2 = v0.y - v0.w;  gx3 = v0.z - v1.x;
        gxr3 = v0.w - v1.y;
        gy0 = s0   + v0.y + 2.0f * v0.x;
        gy1 = v0.x + v0.z + 2.0f * v0.y;
        gy2 = v0.y + v0.w + 2.0f * v0.z;
        gy3 = v0.z + v1.x + 2.0f * v0.w;
    }
    {   // row r = ty+1 : gx weight 2, gy_d top (+)
        ROW_LOAD(ty + 1, s0, v0, v1)
        gx0 += 2.0f * (s0   - v0.y);  gx1 += 2.0f * (v0.x - v0.z);
        gx2 += 2.0f * (v0.y - v0.w);  gx3 += 2.0f * (v0.z - v1.x);
        gxr3 += 2.0f * (v0.w - v1.y);
        gd0 = s0   + v0.y + 2.0f * v0.x;
        gd1 = v0.x + v0.z + 2.0f * v0.y;
        gd2 = v0.y + v0.w + 2.0f * v0.z;
        gd3 = v0.z + v1.x + 2.0f * v0.w;
    }
    {   // row r+1 = ty+2 : gx weight 1, gy bottom (-)
        ROW_LOAD(ty + 2, s0, v0, v1)
        gx0 += s0   - v0.y;  gx1 += v0.x - v0.z;
        gx2 += v0.y - v0.w;  gx3 += v0.z - v1.x;
        gxr3 += v0.w - v1.y;
        gy0 -= s0   + v0.y + 2.0f * v0.x;
        gy1 -= v0.x + v0.z + 2.0f * v0.y;
        gy2 -= v0.y + v0.w + 2.0f * v0.z;
        gy3 -= v0.z + v1.x + 2.0f * v0.w;
    }
    {   // row r+2 = ty+3 : gy_d bottom (-)
        ROW_LOAD(ty + 3, s0, v0, v1)
        gd0 -= s0   + v0.y + 2.0f * v0.x;
        gd1 -= v0.x + v0.z + 2.0f * v0.y;
        gd2 -= v0.y + v0.w + 2.0f * v0.z;
        gd3 -= v0.z + v1.x + 2.0f * v0.w;
    }
#undef ROW_LOAD

    const int h  = h0 + ty;
    const int wb = w0 + tx * OPT;

    float* __restrict__ yb = y + (size_t)b * 2 * IMG_H * IMG_W;
    *reinterpret_cast<float4*>(&yb[(size_t)h * IMG_W + wb]) =
        make_float4(gx0, gx1, gx2, gx3);
    *reinterpret_cast<float4*>(&yb[(size_t)IMG_H * IMG_W + (size_t)h * IMG_W + wb]) =
        make_float4(gy0, gy1, gy2, gy3);

    if (h < IMG_H - 1) {
        const size_t sd = (size_t)(IMG_H - 1) * (IMG_W - 1);
        const size_t o  = (size_t)b * sd + (size_t)h * (IMG_W - 1) + wb;
        // gx_r[k] = gx[k+1] for k<3 (next-column Gx); gxr3 is the only extra diff.
        const float sx0 = fsign(gx0), sx1 = fsign(gx1), sx2 = fsign(gx2), sx3 = fsign(gx3);
        y0[o + 0] = sx0 - sx1;
        y0[o + 1] = sx1 - sx2;
        y0[o + 2] = sx2 - sx3;
        if (wb + 3 < IMG_W - 1) y0[o + 3] = sx3 - fsign(gxr3);
        y1[o + 0] = fsign(gy0) - fsign(gd0);
        y1[o + 1] = fsign(gy1) - fsign(gd1);
        y1[o + 2] = fsign(gy2) - fsign(gd2);
        if (wb + 3 < IMG_W - 1) y1[o + 3] = fsign(gy3) - fsign(gd3);
    }
}

extern "C" void kernel_launch(void* const* d_in, const int* in_sizes, int n_in,
                              void* d_out, int out_size) {
    const float* x = (const float*)d_in[0];
    const int B = in_sizes[0] / (IMG_H * IMG_W);

    float* y  = (float*)d_out;
    float* y0 = y  + (size_t)B * 2 * IMG_H * IMG_W;
    float* y1 = y0 + (size_t)B * (IMG_H - 1) * (IMG_W - 1);

    dim3 block(TXV, TH, 1);
    dim3 grid(IMG_W / TW, IMG_H / TH, B);
    sobel_sign_kernel<<<grid, block>>>(x, y, y0, y1);
}